// round 5
// baseline (speedup 1.0000x reference)
#include <cuda_runtime.h>
#include <cstdint>

// FP8 E4M3 multiplier over "bit-vector" encoded tensors.
// Each fp8 value is 8 float32 bits [s, e3, e2, e1, e0, m2, m1, m0],
// each "bit" float exactly 0.0f (0x00000000) or 1.0f (0x3f800000).
// Integer-domain bit extraction: bit = (raw >> 29) & 1.
// Output bit word = (-bit) & 0x3f800000.
//
// R4: R1 geometry (1 elem/thread, occ ~78%) + integer decode + streaming stores.

__device__ __forceinline__ unsigned bw(int bit) {      // bit(0/1) -> 0.0f/1.0f raw
    return (unsigned)(-bit) & 0x3f800000u;
}

__global__ void __launch_bounds__(256) fp8mul_kernel(
    const uint4* __restrict__ a4,
    const uint4* __restrict__ b4,
    uint4* __restrict__ o4,
    int n)
{
    int i = blockIdx.x * blockDim.x + threadIdx.x;
    if (i >= n) return;

    uint4 alo = a4[2 * i];
    uint4 ahi = a4[2 * i + 1];
    uint4 blo = b4[2 * i];
    uint4 bhi = b4[2 * i + 1];

    // decode: bit = (w >> 29) & 1
    int sa =  (alo.x >> 29) & 1;
    int ea = (((alo.y >> 29) & 1) << 3) | (((alo.z >> 29) & 1) << 2)
           | (((alo.w >> 29) & 1) << 1) |  ((ahi.x >> 29) & 1);
    int ma = (((ahi.y >> 29) & 1) << 2) | (((ahi.z >> 29) & 1) << 1)
           |  ((ahi.w >> 29) & 1);
    int sb =  (blo.x >> 29) & 1;
    int eb = (((blo.y >> 29) & 1) << 3) | (((blo.z >> 29) & 1) << 2)
           | (((blo.w >> 29) & 1) << 1) |  ((bhi.x >> 29) & 1);
    int mb = (((bhi.y >> 29) & 1) << 2) | (((bhi.z >> 29) & 1) << 1)
           |  ((bhi.w >> 29) & 1);

    int sig_a = (ea == 0) ? ma : (ma + 8);
    int sig_b = (eb == 0) ? mb : (mb + 8);
    int exa = ((ea == 0) ? 1 : ea) - 7;
    int exb = ((eb == 0) ? 1 : eb) - 7;

    int M = sig_a * sig_b;          // exact product, <= 225
    int E = exa + exb - 6;          // value = M * 2^E

    int p = (M > 0) ? (31 - __clz(M)) : 0;   // MSB position of M
    int eb_out = E + p + 7;

    // ---- normal path: RNE round to 3 mantissa bits (branch-free) ----
    int sh = p - 3;
    int shp = sh > 0 ? sh : 0;
    int q = M >> shp;
    int rem = M - (q << shp);
    int half = (1 << shp) >> 1;               // 0 when shp==0
    int up = ((rem > half) | ((rem == half) & (q & 1))) & (shp > 0);
    int mant4 = (q + up) << (sh < 0 ? -sh : 0);
    int carry = mant4 >> 4;                   // rounding overflow
    mant4 = (mant4 == 16) ? 8 : mant4;
    int e_n = eb_out + carry;
    int m_n = mant4 - 8;
    int nan = e_n >= 16;
    e_n = nan ? 15 : e_n;
    m_n = nan ? 7 : m_n;

    // ---- subnormal path (eb_out <= 0): mant = RNE(M * 2^(E+9)) ----
    int t = E + 9;
    int shs = (-t) < 0 ? 0 : ((-t) > 30 ? 30 : -t);
    int qs = M >> shs;
    int rems = M - (qs << shs);
    int halfs = (1 << shs) >> 1;
    int ups = ((rems > halfs) | ((rems == halfs) & (qs & 1))) & (shs > 0);
    int mant_s = (qs + ups) << (t > 0 ? t : 0);
    int e_s = (mant_s >= 8) ? 1 : 0;
    int m_s = (mant_s >= 8) ? 0 : mant_s;

    // ---- select ----
    bool is_sub = (eb_out <= 0);
    int e_o = is_sub ? e_s : e_n;
    int m_o = is_sub ? m_s : m_n;
    bool zero = (M == 0);
    e_o = zero ? 0 : e_o;
    m_o = zero ? 0 : m_o;
    int s_o = sa ^ sb;

    uint4 olo, ohi;
    olo.x = bw(s_o);
    olo.y = bw((e_o >> 3) & 1);
    olo.z = bw((e_o >> 2) & 1);
    olo.w = bw((e_o >> 1) & 1);
    ohi.x = bw(e_o & 1);
    ohi.y = bw((m_o >> 2) & 1);
    ohi.z = bw((m_o >> 1) & 1);
    ohi.w = bw(m_o & 1);

    __stcs(&o4[2 * i],     olo);
    __stcs(&o4[2 * i + 1], ohi);
}

extern "C" void kernel_launch(void* const* d_in, const int* in_sizes, int n_in,
                              void* d_out, int out_size)
{
    const uint4* a = (const uint4*)d_in[0];
    const uint4* b = (const uint4*)d_in[1];
    uint4* o = (uint4*)d_out;
    int n = in_sizes[0] / 8;                 // fp8 element count
    int threads = 256;
    int blocks = (n + threads - 1) / threads;
    fp8mul_kernel<<<blocks, threads>>>(a, b, o, n);
}

// round 6
// speedup vs baseline: 1.0411x; 1.0411x over previous
#include <cuda_runtime.h>
#include <cstdint>

// FP8 E4M3 multiplier over "bit-vector" encoded tensors.
// Each fp8 value is 8 float32 bits [s, e3, e2, e1, e0, m2, m1, m0],
// each "bit" float exactly 0.0f (0x00000000) or 1.0f (0x3f800000).
// Integer-domain bit extraction: bit = (raw >> 29) & 1.
// Output bit word = (-bit) & 0x3f800000.
//
// R5: best-measured combo — 1 elem/thread, 256-thread blocks, integer
// decode/encode (24 regs), DEFAULT load/store policy (no .cs hints).
// Pure HBM-bound streaming kernel; traffic is compulsory (384 MiB).

__device__ __forceinline__ unsigned bw(int bit) {      // bit(0/1) -> 0.0f/1.0f raw
    return (unsigned)(-bit) & 0x3f800000u;
}

__global__ void __launch_bounds__(256) fp8mul_kernel(
    const uint4* __restrict__ a4,
    const uint4* __restrict__ b4,
    uint4* __restrict__ o4,
    int n)
{
    int i = blockIdx.x * blockDim.x + threadIdx.x;
    if (i >= n) return;

    uint4 alo = a4[2 * i];
    uint4 ahi = a4[2 * i + 1];
    uint4 blo = b4[2 * i];
    uint4 bhi = b4[2 * i + 1];

    // decode: bit = (w >> 29) & 1
    int sa =  (alo.x >> 29) & 1;
    int ea = (((alo.y >> 29) & 1) << 3) | (((alo.z >> 29) & 1) << 2)
           | (((alo.w >> 29) & 1) << 1) |  ((ahi.x >> 29) & 1);
    int ma = (((ahi.y >> 29) & 1) << 2) | (((ahi.z >> 29) & 1) << 1)
           |  ((ahi.w >> 29) & 1);
    int sb =  (blo.x >> 29) & 1;
    int eb = (((blo.y >> 29) & 1) << 3) | (((blo.z >> 29) & 1) << 2)
           | (((blo.w >> 29) & 1) << 1) |  ((bhi.x >> 29) & 1);
    int mb = (((bhi.y >> 29) & 1) << 2) | (((bhi.z >> 29) & 1) << 1)
           |  ((bhi.w >> 29) & 1);

    int sig_a = (ea == 0) ? ma : (ma + 8);
    int sig_b = (eb == 0) ? mb : (mb + 8);
    int exa = ((ea == 0) ? 1 : ea) - 7;
    int exb = ((eb == 0) ? 1 : eb) - 7;

    int M = sig_a * sig_b;          // exact product, <= 225
    int E = exa + exb - 6;          // value = M * 2^E

    int p = (M > 0) ? (31 - __clz(M)) : 0;   // MSB position of M
    int eb_out = E + p + 7;

    // ---- normal path: RNE round to 3 mantissa bits (branch-free) ----
    int sh = p - 3;
    int shp = sh > 0 ? sh : 0;
    int q = M >> shp;
    int rem = M - (q << shp);
    int half = (1 << shp) >> 1;               // 0 when shp==0
    int up = ((rem > half) | ((rem == half) & (q & 1))) & (shp > 0);
    int mant4 = (q + up) << (sh < 0 ? -sh : 0);
    int carry = mant4 >> 4;                   // rounding overflow
    mant4 = (mant4 == 16) ? 8 : mant4;
    int e_n = eb_out + carry;
    int m_n = mant4 - 8;
    int nan = e_n >= 16;
    e_n = nan ? 15 : e_n;
    m_n = nan ? 7 : m_n;

    // ---- subnormal path (eb_out <= 0): mant = RNE(M * 2^(E+9)) ----
    int t = E + 9;
    int shs = (-t) < 0 ? 0 : ((-t) > 30 ? 30 : -t);
    int qs = M >> shs;
    int rems = M - (qs << shs);
    int halfs = (1 << shs) >> 1;
    int ups = ((rems > halfs) | ((rems == halfs) & (qs & 1))) & (shs > 0);
    int mant_s = (qs + ups) << (t > 0 ? t : 0);
    int e_s = (mant_s >= 8) ? 1 : 0;
    int m_s = (mant_s >= 8) ? 0 : mant_s;

    // ---- select ----
    bool is_sub = (eb_out <= 0);
    int e_o = is_sub ? e_s : e_n;
    int m_o = is_sub ? m_s : m_n;
    bool zero = (M == 0);
    e_o = zero ? 0 : e_o;
    m_o = zero ? 0 : m_o;
    int s_o = sa ^ sb;

    uint4 olo, ohi;
    olo.x = bw(s_o);
    olo.y = bw((e_o >> 3) & 1);
    olo.z = bw((e_o >> 2) & 1);
    olo.w = bw((e_o >> 1) & 1);
    ohi.x = bw(e_o & 1);
    ohi.y = bw((m_o >> 2) & 1);
    ohi.z = bw((m_o >> 1) & 1);
    ohi.w = bw(m_o & 1);

    o4[2 * i]     = olo;
    o4[2 * i + 1] = ohi;
}

extern "C" void kernel_launch(void* const* d_in, const int* in_sizes, int n_in,
                              void* d_out, int out_size)
{
    const uint4* a = (const uint4*)d_in[0];
    const uint4* b = (const uint4*)d_in[1];
    uint4* o = (uint4*)d_out;
    int n = in_sizes[0] / 8;                 // fp8 element count
    int threads = 256;
    int blocks = (n + threads - 1) / threads;
    fp8mul_kernel<<<blocks, threads>>>(a, b, o, n);
}